// round 11
// baseline (speedup 1.0000x reference)
#include <cuda_runtime.h>
#include <cuda_fp16.h>
#include <cstdint>

// ---------------------------------------------------------------------------
// DWT_Features on GB300 (sm_103 PTX: mma.sync path):
//   k_mbuild: build 84x64 DWT matrix M once -> g_M; reset split-K counters
//   k_weff:   fold M into conv weights (FFMA2) -> W_eff fp16 [s*128+n][k]
//   k_gemm:   split-K=4 partial GEMM, single-pass fp16, BM=128 BN=128 BK=32;
//             FUSED finalize: last CTA per (s,mtile) reduces 4 partials,
//             adds bias, leaky-ReLU, writes out.
// ---------------------------------------------------------------------------

#define B_DIM    2048
#define SW_DIM   4
#define KF       128
#define DWT_LEN  84
#define KDIM     4096
#define KSPLIT   4
#define KQ       (KDIM / KSPLIT)   // 1024
#define OUTC     512
#define BK       32
#define NCHUNK   (KQ / BK)         // 32
#define BM       128
#define NMTILE   (B_DIM / BM)      // 16

// smem rows: 32 halves + 8 pad = 80 B (stride 5 x16B, coprime 8 -> ldsm clean)
#define ROWB     80
#define TILEB    10240             // 128*80
#define AOFF(j)  ((j) * TILEB)                 // j in {0,1}
#define BOFF(j)  (2 * TILEB + (j) * TILEB)     // j in {0,1,2}
#define DSMEM    (5 * TILEB)       // 51200

__constant__ float c_dec_lo[8] = {
    -0.010597401784997278f,  0.032883011666982945f,  0.030841381835986965f,
    -0.18703481171888114f,  -0.02798376941698385f,   0.6308807679295904f,
     0.7148465705525415f,    0.23037781330885523f };
__constant__ float c_dec_hi[8] = {
    -0.23037781330885523f,   0.7148465705525415f,   -0.6308807679295904f,
    -0.02798376941698385f,   0.18703481171888114f,   0.030841381835986965f,
    -0.032883011666982945f, -0.010597401784997278f };

__device__ float g_M[DWT_LEN * 64];                               // 84 x 64
__device__ __align__(16) __half g_W[SW_DIM * KF * KDIM];          // [s*128+n][k]
__device__ __align__(16) float g_part[KSPLIT][B_DIM][OUTC];       // 16.8 MB
__device__ int g_cnt[SW_DIM][NMTILE];                             // split-K ctrs

// ---------------------------------------------------------------------------
__device__ __forceinline__ uint32_t smem_u32(const void* p) {
    uint32_t a;
    asm("{ .reg .u64 t; cvta.to.shared.u64 t, %1; cvt.u32.u64 %0, t; }"
        : "=r"(a) : "l"(p));
    return a;
}
__device__ __forceinline__ void cp16(uint32_t dst, const void* src) {
    asm volatile("cp.async.cg.shared.global [%0], [%1], 16;"
                 :: "r"(dst), "l"(src) : "memory");
}
__device__ __forceinline__ void ldsm4(uint32_t* r, uint32_t addr) {
    asm volatile("ldmatrix.sync.aligned.m8n8.x4.shared.b16 {%0,%1,%2,%3}, [%4];"
                 : "=r"(r[0]), "=r"(r[1]), "=r"(r[2]), "=r"(r[3]) : "r"(addr));
}
__device__ __forceinline__ void mma_f16(float* c, const uint32_t* a,
                                        const uint32_t* b) {
    asm volatile(
        "mma.sync.aligned.m16n8k16.row.col.f32.f16.f16.f32 "
        "{%0,%1,%2,%3}, {%4,%5,%6,%7}, {%8,%9}, {%0,%1,%2,%3};"
        : "+f"(c[0]), "+f"(c[1]), "+f"(c[2]), "+f"(c[3])
        : "r"(a[0]), "r"(a[1]), "r"(a[2]), "r"(a[3]), "r"(b[0]), "r"(b[1]));
}
__device__ __forceinline__ unsigned long long pack2(float x, float y) {
    unsigned long long r;
    asm("mov.b64 %0, {%1, %2};" : "=l"(r) : "f"(x), "f"(y));
    return r;
}
__device__ __forceinline__ void fma2(unsigned long long& d,
                                     unsigned long long a,
                                     unsigned long long b) {
    asm("fma.rn.f32x2 %0, %1, %2, %3;" : "=l"(d) : "l"(a), "l"(b), "l"(d));
}
__device__ __forceinline__ void unpack2(unsigned long long v, float& x, float& y) {
    asm("mov.b64 {%0, %1}, %2;" : "=f"(x), "=f"(y) : "l"(v));
}

// ---------------------------------------------------------------------------
// k_mbuild: build 84x64 DWT matrix once; reset split-K counters.
// ---------------------------------------------------------------------------
__global__ void __launch_bounds__(256)
k_mbuild() {
    __shared__ float L1[35 * 64], L2[21 * 64];
    const int tid = threadIdx.x;

    if (tid < SW_DIM * NMTILE) ((int*)g_cnt)[tid] = 0;

    for (int e = tid; e < 35 * 64; e += 256) {
        int j = e >> 6, tau = e & 63;
        float sl = 0.f, sh = 0.f;
        #pragma unroll
        for (int i = 0; i < 8; i++) {
            int idx = 2 * j + i - 6;
            if (idx < 0) idx = -idx;
            if (idx > 63) idx = 126 - idx;
            if (idx == tau) { sl += c_dec_lo[7 - i]; sh += c_dec_hi[7 - i]; }
        }
        L1[j * 64 + tau] = sl;
        g_M[(14 + j) * 64 + tau] = sh;
    }
    __syncthreads();

    for (int e = tid; e < 21 * 64; e += 256) {
        int j = e >> 6, tau = e & 63;
        float sl = 0.f, sh = 0.f;
        #pragma unroll
        for (int i = 0; i < 8; i++) {
            int idx = 2 * j + i - 6;
            if (idx < 0) idx = -idx;
            if (idx > 35) idx = 70 - idx;
            if (idx < 35) {
                float v = L1[idx * 64 + tau];
                sl += v * c_dec_lo[7 - i];
                sh += v * c_dec_hi[7 - i];
            }
        }
        L2[j * 64 + tau] = sl;
        g_M[(49 + j) * 64 + tau] = sh;
    }
    __syncthreads();

    for (int e = tid; e < 14 * 64; e += 256) {
        int j = e >> 6, tau = e & 63;
        float sl = 0.f, sh = 0.f;
        #pragma unroll
        for (int i = 0; i < 8; i++) {
            int idx = 2 * j + i - 6;
            if (idx < 0) idx = -idx;
            if (idx > 21) idx = 42 - idx;
            if (idx < 21) {
                float v = L2[idx * 64 + tau];
                sl += v * c_dec_lo[7 - i];
                sh += v * c_dec_hi[7 - i];
            }
        }
        g_M[j * 64 + tau] = sl;
        g_M[(70 + j) * 64 + tau] = sh;
    }
}

// ---------------------------------------------------------------------------
// k_weff: pure fold (verified). one block per sn = s*128+n.
// ---------------------------------------------------------------------------
#define WEFF_SMEM 43008

__global__ void __launch_bounds__(256)
k_weff(const float* __restrict__ cw) {
    extern __shared__ float wsm[];
    float* Ms = wsm;
    float* Ws = wsm + 5376;

    const int tid = threadIdx.x;
    const int sn = blockIdx.x;
    const float* src = cw + (size_t)sn * (DWT_LEN * 64);

    {
        uint32_t msa = smem_u32(Ms);
        uint32_t wsa = smem_u32(Ws);
        for (int i = tid; i < (DWT_LEN * 64) / 4; i += 256) {
            cp16(msa + i * 16, g_M + i * 4);
            cp16(wsa + i * 16, src + i * 4);
        }
        asm volatile("cp.async.commit_group;" ::: "memory");
        asm volatile("cp.async.wait_group 0;" ::: "memory");
    }
    __syncthreads();

    const int tau0 = (tid >> 4) << 2;
    const int hw0 = (tid & 15) << 2;
    unsigned long long acc2[4][2];
    #pragma unroll
    for (int a = 0; a < 4; a++) { acc2[a][0] = 0ull; acc2[a][1] = 0ull; }

    #pragma unroll 4
    for (int t = 0; t < DWT_LEN; t++) {
        float4 mv = *(const float4*)&Ms[t * 64 + tau0];
        ulonglong2 wv = *(const ulonglong2*)&Ws[t * 64 + hw0];
        unsigned long long m0 = pack2(mv.x, mv.x);
        unsigned long long m1 = pack2(mv.y, mv.y);
        unsigned long long m2 = pack2(mv.z, mv.z);
        unsigned long long m3 = pack2(mv.w, mv.w);
        fma2(acc2[0][0], m0, wv.x); fma2(acc2[0][1], m0, wv.y);
        fma2(acc2[1][0], m1, wv.x); fma2(acc2[1][1], m1, wv.y);
        fma2(acc2[2][0], m2, wv.x); fma2(acc2[2][1], m2, wv.y);
        fma2(acc2[3][0], m3, wv.x); fma2(acc2[3][1], m3, wv.y);
    }

    __half* dst = g_W + (size_t)sn * KDIM;
    #pragma unroll
    for (int a = 0; a < 4; a++) {
        float v0, v1, v2, v3;
        unpack2(acc2[a][0], v0, v1);
        unpack2(acc2[a][1], v2, v3);
        __half2 h01 = __float22half2_rn(make_float2(v0, v1));
        __half2 h23 = __float22half2_rn(make_float2(v2, v3));
        *(uint2*)&dst[(tau0 + a) * 64 + hw0] =
            make_uint2(*(uint32_t*)&h01, *(uint32_t*)&h23);
    }
}

// ---------------------------------------------------------------------------
// k_gemm: BM=128, BN=128, BK=32, split-K=4. 256 threads = 8 warps (2m x 4n),
// warp tile 64x32. ONE __syncthreads per chunk; A 2-buf, B 3-buf.
// FUSED finalize via last-CTA reduction.
// ---------------------------------------------------------------------------
#define ISSUE_B(K0, STOFF) do {                                              \
    uint32_t _st = sbase + (STOFF);                                          \
    _Pragma("unroll")                                                        \
    for (int _it = 0; _it < 2; _it++) {                                      \
        int _idx = tid + _it * 256;                                          \
        int _n = _idx >> 2, _seg = _idx & 3;                                 \
        cp16(_st + _n * ROWB + _seg * 16,                                    \
             WB + (size_t)_n * KDIM + (K0) + _seg * 8);                      \
    }                                                                        \
    asm volatile("cp.async.commit_group;" ::: "memory");                     \
} while (0)

#define LDG_A(K0) do {                                                       \
    _Pragma("unroll")                                                        \
    for (int _it = 0; _it < 4; _it++) {                                      \
        int _idx = tid + _it * 256;                                          \
        int _row = _idx >> 3, _seg = _idx & 7;                               \
        areg[_it] = *(const float4*)(Abase +                                 \
            (size_t)_row * (SW_DIM * KDIM) + (K0) + _seg * 4);               \
    }                                                                        \
} while (0)

#define STS_A(STOFF) do {                                                    \
    char* _pb = sm + (STOFF);                                                \
    _Pragma("unroll")                                                        \
    for (int _it = 0; _it < 4; _it++) {                                      \
        int _idx = tid + _it * 256;                                          \
        int _row = _idx >> 3, _seg = _idx & 7;                               \
        float4 _v = areg[_it];                                               \
        __half2 _h01 = __float22half2_rn(make_float2(_v.x, _v.y));           \
        __half2 _h23 = __float22half2_rn(make_float2(_v.z, _v.w));           \
        *(uint2*)(_pb + _row * ROWB + _seg * 8) =                            \
            make_uint2(*(uint32_t*)&_h01, *(uint32_t*)&_h23);                \
    }                                                                        \
} while (0)

__global__ void __launch_bounds__(256, 2)
k_gemm(const float* __restrict__ x, const float* __restrict__ bias,
       float* __restrict__ out) {
    extern __shared__ char sm[];
    const int tid = threadIdx.x;
    const int wid = tid >> 5, lid = tid & 31;
    const int s = blockIdx.x >> 2;
    const int ks = blockIdx.x & 3;
    const int m0 = blockIdx.y * BM;
    const int kbase = ks * KQ;
    const int wm = wid & 1, wn = wid >> 1;

    const uint32_t sbase = smem_u32(sm);
    const float* Abase = x + (size_t)m0 * (SW_DIM * KDIM) + (size_t)s * KDIM
                         + kbase;
    const __half* WB = g_W + (size_t)s * KF * KDIM + kbase;

    const int q = lid >> 3, r = lid & 7;
    const uint32_t laneA = (wm * 64 + (q & 1) * 8 + r) * ROWB + (q >> 1) * 16;
    const uint32_t laneB = (wn * 32 + (q >> 1) * 8 + r) * ROWB + (q & 1) * 16;

    float acc[4][4][4];
    #pragma unroll
    for (int a = 0; a < 4; a++)
        #pragma unroll
        for (int b = 0; b < 4; b++)
            #pragma unroll
            for (int c = 0; c < 4; c++) acc[a][b][c] = 0.f;

    float4 areg[4];

    // prologue: B(0), B(1) in flight; A(0) staged; areg = A(1)
    ISSUE_B(0, BOFF(0));
    ISSUE_B(BK, BOFF(1));
    LDG_A(0);
    STS_A(AOFF(0));
    LDG_A(BK);
    asm volatile("cp.async.wait_group 1;" ::: "memory");
    __syncthreads();

    for (int i = 0; i < NCHUNK; i++) {
        if (i + 2 < NCHUNK) ISSUE_B((i + 2) * BK, BOFF((i + 2) % 3));

        const uint32_t stA = sbase + AOFF(i & 1);
        const uint32_t stB = sbase + BOFF(i % 3);
        #pragma unroll
        for (int kk = 0; kk < 2; kk++) {
            const uint32_t ka = kk * 32;
            uint32_t Af[4][4], B0[4], B1[4];
            ldsm4(B0, stB + laneB + ka);
            ldsm4(B1, stB + laneB + ka + 16 * ROWB);
            #pragma unroll
            for (int mf = 0; mf < 4; mf++)
                ldsm4(Af[mf], stA + laneA + mf * (16 * ROWB) + ka);
            #pragma unroll
            for (int mf = 0; mf < 4; mf++) {
                #pragma unroll
                for (int nf = 0; nf < 4; nf++) {
                    const uint32_t* bb = ((nf & 2) ? B1 : B0) + (nf & 1) * 2;
                    mma_f16(acc[mf][nf], Af[mf], bb);
                }
            }
        }

        if (i + 1 < NCHUNK) STS_A(AOFF((i + 1) & 1));
        if (i + 2 < NCHUNK) {
            LDG_A((i + 2) * BK);
            asm volatile("cp.async.wait_group 1;" ::: "memory");
        } else {
            asm volatile("cp.async.wait_group 0;" ::: "memory");
        }
        __syncthreads();
    }

    // write fp32 partial
    {
        const int g = lid >> 2, tc = lid & 3;
        float* pbase = &g_part[ks][0][0];
        #pragma unroll
        for (int mf = 0; mf < 4; mf++) {
            const int row = m0 + wm * 64 + mf * 16 + g;
            #pragma unroll
            for (int nf = 0; nf < 4; nf++) {
                const int col = s * KF + wn * 32 + nf * 8 + tc * 2;
                *(float2*)&pbase[(size_t)row * OUTC + col] =
                    make_float2(acc[mf][nf][0], acc[mf][nf][1]);
                *(float2*)&pbase[(size_t)(row + 8) * OUTC + col] =
                    make_float2(acc[mf][nf][2], acc[mf][nf][3]);
            }
        }
    }

    // last CTA of this (s, mtile) group reduces the 4 partials
    __shared__ int sLast;
    __threadfence();
    if (tid == 0) {
        int old = atomicAdd(&g_cnt[s][blockIdx.y], 1);
        sLast = (old == KSPLIT - 1) ? 1 : 0;
    }
    __syncthreads();
    if (sLast) {
        __threadfence();
        // tile: rows m0..m0+127, cols s*128..s*128+127 (32 float4 per row)
        for (int idx = tid; idx < (BM * KF) / 4; idx += 256) {
            int rr = idx >> 5;
            int cc = (idx & 31) * 4;
            size_t off = (size_t)(m0 + rr) * OUTC + s * KF + cc;
            float4 a = *(const float4*)(&g_part[0][0][0] + off);
            float4 b = *(const float4*)(&g_part[1][0][0] + off);
            float4 c = *(const float4*)(&g_part[2][0][0] + off);
            float4 d = *(const float4*)(&g_part[3][0][0] + off);
            float4 bb = *(const float4*)&bias[s * KF + cc];
            float v0 = (a.x + b.x) + (c.x + d.x) + bb.x;
            float v1 = (a.y + b.y) + (c.y + d.y) + bb.y;
            float v2 = (a.z + b.z) + (c.z + d.z) + bb.z;
            float v3 = (a.w + b.w) + (c.w + d.w) + bb.w;
            v0 = v0 > 0.f ? v0 : 0.01f * v0;
            v1 = v1 > 0.f ? v1 : 0.01f * v1;
            v2 = v2 > 0.f ? v2 : 0.01f * v2;
            v3 = v3 > 0.f ? v3 : 0.01f * v3;
            *(float4*)(out + off) = make_float4(v0, v1, v2, v3);
        }
    }
}

// ---------------------------------------------------------------------------
extern "C" void kernel_launch(void* const* d_in, const int* in_sizes, int n_in,
                              void* d_out, int out_size) {
    const float* x    = (const float*)d_in[0];   // [2048,1,256,8,8]
    const float* cw   = (const float*)d_in[1];   // [4,128,84,8,8]
    const float* bias = (const float*)d_in[2];   // [4,128]
    float* out = (float*)d_out;                  // [2048,512]

    cudaFuncSetAttribute(k_weff, cudaFuncAttributeMaxDynamicSharedMemorySize,
                         WEFF_SMEM);
    cudaFuncSetAttribute(k_gemm, cudaFuncAttributeMaxDynamicSharedMemorySize,
                         DSMEM);

    k_mbuild<<<1, 256>>>();
    k_weff<<<SW_DIM * KF, 256, WEFF_SMEM>>>(cw);
    dim3 grid(SW_DIM * KSPLIT, B_DIM / BM);
    k_gemm<<<grid, 256, DSMEM>>>(x, bias, out);
}

// round 12
// speedup vs baseline: 1.1130x; 1.1130x over previous
#include <cuda_runtime.h>
#include <cuda_fp16.h>
#include <cstdint>

// ---------------------------------------------------------------------------
// DWT_Features on GB300 (sm_103 PTX: mma.sync path):
//   g_Mt:   84x64 DWT analysis matrix, built at COMPILE TIME (constexpr)
//   k_weff: fold M into conv weights (FFMA2) -> W_eff fp16 [s*128+n][k]
//   k_gemm: split-K=4 partial GEMM, single-pass fp16, BM=128 BN=128 BK=32
//   k_fin:  out = leaky(p0+p1+p2+p3 + bias)
// ---------------------------------------------------------------------------

#define B_DIM    2048
#define SW_DIM   4
#define KF       128
#define DWT_LEN  84
#define KDIM     4096
#define KSPLIT   4
#define KQ       (KDIM / KSPLIT)   // 1024
#define OUTC     512
#define BK       32
#define NCHUNK   (KQ / BK)         // 32
#define BM       128

// smem rows: 32 halves + 8 pad = 80 B (stride 5 x16B, coprime 8 -> ldsm clean)
#define ROWB     80
#define TILEB    10240             // 128*80
#define AOFF(j)  ((j) * TILEB)                 // j in {0,1}
#define BOFF(j)  (2 * TILEB + (j) * TILEB)     // j in {0,1,2}
#define DSMEM    (5 * TILEB)       // 51200

// ---------------------------------------------------------------------------
// Compile-time DWT matrix (mirrors reference _dwt_level exactly; same logic
// verified on-device R7-R10). Strict IEEE fp32 at compile time.
// ---------------------------------------------------------------------------
struct MTab { float m[DWT_LEN * 64]; };

constexpr float DEC_LO[8] = {
    -0.010597401784997278f,  0.032883011666982945f,  0.030841381835986965f,
    -0.18703481171888114f,  -0.02798376941698385f,   0.6308807679295904f,
     0.7148465705525415f,    0.23037781330885523f };
constexpr float DEC_HI[8] = {
    -0.23037781330885523f,   0.7148465705525415f,   -0.6308807679295904f,
    -0.02798376941698385f,   0.18703481171888114f,   0.030841381835986965f,
    -0.032883011666982945f, -0.010597401784997278f };

constexpr MTab build_m() {
    MTab t{};
    float L1[35][64] = {};
    float L2[21][64] = {};
    // level 1: N=64 (even pad), reflect at 0 / 63
    for (int j = 0; j < 35; j++)
        for (int tau = 0; tau < 64; tau++) {
            float sl = 0.f, sh = 0.f;
            for (int i = 0; i < 8; i++) {
                int idx = 2 * j + i - 6;
                if (idx < 0) idx = -idx;
                if (idx > 63) idx = 126 - idx;
                if (idx == tau) { sl += DEC_LO[7 - i]; sh += DEC_HI[7 - i]; }
            }
            L1[j][tau] = sl;
            t.m[(14 + j) * 64 + tau] = sh;
        }
    // level 2: N=35 (odd pad -> zero at idx 35), reflect at 35
    for (int j = 0; j < 21; j++)
        for (int tau = 0; tau < 64; tau++) {
            float sl = 0.f, sh = 0.f;
            for (int i = 0; i < 8; i++) {
                int idx = 2 * j + i - 6;
                if (idx < 0) idx = -idx;
                if (idx > 35) idx = 70 - idx;
                if (idx < 35) {
                    float v = L1[idx][tau];
                    sl += v * DEC_LO[7 - i];
                    sh += v * DEC_HI[7 - i];
                }
            }
            L2[j][tau] = sl;
            t.m[(49 + j) * 64 + tau] = sh;
        }
    // level 3: N=21 (odd pad -> zero at idx 21), reflect at 21
    for (int j = 0; j < 14; j++)
        for (int tau = 0; tau < 64; tau++) {
            float sl = 0.f, sh = 0.f;
            for (int i = 0; i < 8; i++) {
                int idx = 2 * j + i - 6;
                if (idx < 0) idx = -idx;
                if (idx > 21) idx = 42 - idx;
                if (idx < 21) {
                    float v = L2[idx][tau];
                    sl += v * DEC_LO[7 - i];
                    sh += v * DEC_HI[7 - i];
                }
            }
            t.m[j * 64 + tau] = sl;
            t.m[(70 + j) * 64 + tau] = sh;
        }
    return t;
}

__device__ __align__(16) const MTab g_Mt = build_m();

__device__ __align__(16) __half g_W[SW_DIM * KF * KDIM];          // [s*128+n][k]
__device__ __align__(16) float g_part[KSPLIT][B_DIM][OUTC];       // 16.8 MB

// ---------------------------------------------------------------------------
__device__ __forceinline__ uint32_t smem_u32(const void* p) {
    uint32_t a;
    asm("{ .reg .u64 t; cvta.to.shared.u64 t, %1; cvt.u32.u64 %0, t; }"
        : "=r"(a) : "l"(p));
    return a;
}
__device__ __forceinline__ void cp16(uint32_t dst, const void* src) {
    asm volatile("cp.async.cg.shared.global [%0], [%1], 16;"
                 :: "r"(dst), "l"(src) : "memory");
}
__device__ __forceinline__ void ldsm4(uint32_t* r, uint32_t addr) {
    asm volatile("ldmatrix.sync.aligned.m8n8.x4.shared.b16 {%0,%1,%2,%3}, [%4];"
                 : "=r"(r[0]), "=r"(r[1]), "=r"(r[2]), "=r"(r[3]) : "r"(addr));
}
__device__ __forceinline__ void mma_f16(float* c, const uint32_t* a,
                                        const uint32_t* b) {
    asm volatile(
        "mma.sync.aligned.m16n8k16.row.col.f32.f16.f16.f32 "
        "{%0,%1,%2,%3}, {%4,%5,%6,%7}, {%8,%9}, {%0,%1,%2,%3};"
        : "+f"(c[0]), "+f"(c[1]), "+f"(c[2]), "+f"(c[3])
        : "r"(a[0]), "r"(a[1]), "r"(a[2]), "r"(a[3]), "r"(b[0]), "r"(b[1]));
}
__device__ __forceinline__ unsigned long long pack2(float x, float y) {
    unsigned long long r;
    asm("mov.b64 %0, {%1, %2};" : "=l"(r) : "f"(x), "f"(y));
    return r;
}
__device__ __forceinline__ void fma2(unsigned long long& d,
                                     unsigned long long a,
                                     unsigned long long b) {
    asm("fma.rn.f32x2 %0, %1, %2, %3;" : "=l"(d) : "l"(a), "l"(b), "l"(d));
}
__device__ __forceinline__ void unpack2(unsigned long long v, float& x, float& y) {
    asm("mov.b64 {%0, %1}, %2;" : "=f"(x), "=f"(y) : "l"(v));
}

// ---------------------------------------------------------------------------
// k_weff: pure fold (verified). one block per sn = s*128+n.
// ---------------------------------------------------------------------------
#define WEFF_SMEM 43008

__global__ void __launch_bounds__(256)
k_weff(const float* __restrict__ cw) {
    extern __shared__ float wsm[];
    float* Ms = wsm;
    float* Ws = wsm + 5376;

    const int tid = threadIdx.x;
    const int sn = blockIdx.x;
    const float* src = cw + (size_t)sn * (DWT_LEN * 64);

    {
        uint32_t msa = smem_u32(Ms);
        uint32_t wsa = smem_u32(Ws);
        for (int i = tid; i < (DWT_LEN * 64) / 4; i += 256) {
            cp16(msa + i * 16, g_Mt.m + i * 4);
            cp16(wsa + i * 16, src + i * 4);
        }
        asm volatile("cp.async.commit_group;" ::: "memory");
        asm volatile("cp.async.wait_group 0;" ::: "memory");
    }
    __syncthreads();

    const int tau0 = (tid >> 4) << 2;
    const int hw0 = (tid & 15) << 2;
    unsigned long long acc2[4][2];
    #pragma unroll
    for (int a = 0; a < 4; a++) { acc2[a][0] = 0ull; acc2[a][1] = 0ull; }

    #pragma unroll 4
    for (int t = 0; t < DWT_LEN; t++) {
        float4 mv = *(const float4*)&Ms[t * 64 + tau0];
        ulonglong2 wv = *(const ulonglong2*)&Ws[t * 64 + hw0];
        unsigned long long m0 = pack2(mv.x, mv.x);
        unsigned long long m1 = pack2(mv.y, mv.y);
        unsigned long long m2 = pack2(mv.z, mv.z);
        unsigned long long m3 = pack2(mv.w, mv.w);
        fma2(acc2[0][0], m0, wv.x); fma2(acc2[0][1], m0, wv.y);
        fma2(acc2[1][0], m1, wv.x); fma2(acc2[1][1], m1, wv.y);
        fma2(acc2[2][0], m2, wv.x); fma2(acc2[2][1], m2, wv.y);
        fma2(acc2[3][0], m3, wv.x); fma2(acc2[3][1], m3, wv.y);
    }

    __half* dst = g_W + (size_t)sn * KDIM;
    #pragma unroll
    for (int a = 0; a < 4; a++) {
        float v0, v1, v2, v3;
        unpack2(acc2[a][0], v0, v1);
        unpack2(acc2[a][1], v2, v3);
        __half2 h01 = __float22half2_rn(make_float2(v0, v1));
        __half2 h23 = __float22half2_rn(make_float2(v2, v3));
        *(uint2*)&dst[(tau0 + a) * 64 + hw0] =
            make_uint2(*(uint32_t*)&h01, *(uint32_t*)&h23);
    }
}

// ---------------------------------------------------------------------------
// k_gemm: BM=128, BN=128, BK=32, split-K=4. 256 threads = 8 warps (2m x 4n),
// warp tile 64x32. ONE __syncthreads per chunk; A 2-buf, B 3-buf. (R10, 61.5us)
// ---------------------------------------------------------------------------
#define ISSUE_B(K0, STOFF) do {                                              \
    uint32_t _st = sbase + (STOFF);                                          \
    _Pragma("unroll")                                                        \
    for (int _it = 0; _it < 2; _it++) {                                      \
        int _idx = tid + _it * 256;                                          \
        int _n = _idx >> 2, _seg = _idx & 3;                                 \
        cp16(_st + _n * ROWB + _seg * 16,                                    \
             WB + (size_t)_n * KDIM + (K0) + _seg * 8);                      \
    }                                                                        \
    asm volatile("cp.async.commit_group;" ::: "memory");                     \
} while (0)

#define LDG_A(K0) do {                                                       \
    _Pragma("unroll")                                                        \
    for (int _it = 0; _it < 4; _it++) {                                      \
        int _idx = tid + _it * 256;                                          \
        int _row = _idx >> 3, _seg = _idx & 7;                               \
        areg[_it] = *(const float4*)(Abase +                                 \
            (size_t)_row * (SW_DIM * KDIM) + (K0) + _seg * 4);               \
    }                                                                        \
} while (0)

#define STS_A(STOFF) do {                                                    \
    char* _pb = sm + (STOFF);                                                \
    _Pragma("unroll")                                                        \
    for (int _it = 0; _it < 4; _it++) {                                      \
        int _idx = tid + _it * 256;                                          \
        int _row = _idx >> 3, _seg = _idx & 7;                               \
        float4 _v = areg[_it];                                               \
        __half2 _h01 = __float22half2_rn(make_float2(_v.x, _v.y));           \
        __half2 _h23 = __float22half2_rn(make_float2(_v.z, _v.w));           \
        *(uint2*)(_pb + _row * ROWB + _seg * 8) =                            \
            make_uint2(*(uint32_t*)&_h01, *(uint32_t*)&_h23);                \
    }                                                                        \
} while (0)

__global__ void __launch_bounds__(256, 2)
k_gemm(const float* __restrict__ x) {
    extern __shared__ char sm[];
    const int tid = threadIdx.x;
    const int wid = tid >> 5, lid = tid & 31;
    const int s = blockIdx.x >> 2;
    const int ks = blockIdx.x & 3;
    const int m0 = blockIdx.y * BM;
    const int kbase = ks * KQ;
    const int wm = wid & 1, wn = wid >> 1;

    const uint32_t sbase = smem_u32(sm);
    const float* Abase = x + (size_t)m0 * (SW_DIM * KDIM) + (size_t)s * KDIM
                         + kbase;
    const __half* WB = g_W + (size_t)s * KF * KDIM + kbase;

    const int q = lid >> 3, r = lid & 7;
    const uint32_t laneA = (wm * 64 + (q & 1) * 8 + r) * ROWB + (q >> 1) * 16;
    const uint32_t laneB = (wn * 32 + (q >> 1) * 8 + r) * ROWB + (q & 1) * 16;

    float acc[4][4][4];
    #pragma unroll
    for (int a = 0; a < 4; a++)
        #pragma unroll
        for (int b = 0; b < 4; b++)
            #pragma unroll
            for (int c = 0; c < 4; c++) acc[a][b][c] = 0.f;

    float4 areg[4];

    // prologue: B(0), B(1) in flight; A(0) staged; areg = A(1)
    ISSUE_B(0, BOFF(0));
    ISSUE_B(BK, BOFF(1));
    LDG_A(0);
    STS_A(AOFF(0));
    LDG_A(BK);
    asm volatile("cp.async.wait_group 1;" ::: "memory");
    __syncthreads();

    for (int i = 0; i < NCHUNK; i++) {
        if (i + 2 < NCHUNK) ISSUE_B((i + 2) * BK, BOFF((i + 2) % 3));

        const uint32_t stA = sbase + AOFF(i & 1);
        const uint32_t stB = sbase + BOFF(i % 3);
        #pragma unroll
        for (int kk = 0; kk < 2; kk++) {
            const uint32_t ka = kk * 32;
            uint32_t Af[4][4], B0[4], B1[4];
            ldsm4(B0, stB + laneB + ka);
            ldsm4(B1, stB + laneB + ka + 16 * ROWB);
            #pragma unroll
            for (int mf = 0; mf < 4; mf++)
                ldsm4(Af[mf], stA + laneA + mf * (16 * ROWB) + ka);
            #pragma unroll
            for (int mf = 0; mf < 4; mf++) {
                #pragma unroll
                for (int nf = 0; nf < 4; nf++) {
                    const uint32_t* bb = ((nf & 2) ? B1 : B0) + (nf & 1) * 2;
                    mma_f16(acc[mf][nf], Af[mf], bb);
                }
            }
        }

        if (i + 1 < NCHUNK) STS_A(AOFF((i + 1) & 1));
        if (i + 2 < NCHUNK) {
            LDG_A((i + 2) * BK);
            asm volatile("cp.async.wait_group 1;" ::: "memory");
        } else {
            asm volatile("cp.async.wait_group 0;" ::: "memory");
        }
        __syncthreads();
    }

    // write fp32 partial (no bias/relu)
    const int g = lid >> 2, tc = lid & 3;
    float* pbase = &g_part[ks][0][0];
    #pragma unroll
    for (int mf = 0; mf < 4; mf++) {
        const int row = m0 + wm * 64 + mf * 16 + g;
        #pragma unroll
        for (int nf = 0; nf < 4; nf++) {
            const int col = s * KF + wn * 32 + nf * 8 + tc * 2;
            *(float2*)&pbase[(size_t)row * OUTC + col] =
                make_float2(acc[mf][nf][0], acc[mf][nf][1]);
            *(float2*)&pbase[(size_t)(row + 8) * OUTC + col] =
                make_float2(acc[mf][nf][2], acc[mf][nf][3]);
        }
    }
}

// ---------------------------------------------------------------------------
// finalize: out = leaky(p0+p1+p2+p3 + bias); 2 float4 per thread
// ---------------------------------------------------------------------------
__global__ void __launch_bounds__(256)
k_fin(const float* __restrict__ bias, float* __restrict__ out) {
    #pragma unroll
    for (int u = 0; u < 2; u++) {
        int i = (blockIdx.x * 2 + u) * 256 + threadIdx.x;   // float4 index
        float4 a = *(const float4*)(&g_part[0][0][0] + (size_t)i * 4);
        float4 b = *(const float4*)(&g_part[1][0][0] + (size_t)i * 4);
        float4 c = *(const float4*)(&g_part[2][0][0] + (size_t)i * 4);
        float4 d = *(const float4*)(&g_part[3][0][0] + (size_t)i * 4);
        int col = (i * 4) & (OUTC - 1);
        float4 bb = *(const float4*)&bias[col];
        float v0 = (a.x + b.x) + (c.x + d.x) + bb.x;
        float v1 = (a.y + b.y) + (c.y + d.y) + bb.y;
        float v2 = (a.z + b.z) + (c.z + d.z) + bb.z;
        float v3 = (a.w + b.w) + (c.w + d.w) + bb.w;
        v0 = v0 > 0.f ? v0 : 0.01f * v0;
        v1 = v1 > 0.f ? v1 : 0.01f * v1;
        v2 = v2 > 0.f ? v2 : 0.01f * v2;
        v3 = v3 > 0.f ? v3 : 0.01f * v3;
        *(float4*)&out[(size_t)i * 4] = make_float4(v0, v1, v2, v3);
    }
}

// ---------------------------------------------------------------------------
extern "C" void kernel_launch(void* const* d_in, const int* in_sizes, int n_in,
                              void* d_out, int out_size) {
    const float* x    = (const float*)d_in[0];   // [2048,1,256,8,8]
    const float* cw   = (const float*)d_in[1];   // [4,128,84,8,8]
    const float* bias = (const float*)d_in[2];   // [4,128]
    float* out = (float*)d_out;                  // [2048,512]

    cudaFuncSetAttribute(k_weff, cudaFuncAttributeMaxDynamicSharedMemorySize,
                         WEFF_SMEM);
    cudaFuncSetAttribute(k_gemm, cudaFuncAttributeMaxDynamicSharedMemorySize,
                         DSMEM);

    k_weff<<<SW_DIM * KF, 256, WEFF_SMEM>>>(cw);
    dim3 grid(SW_DIM * KSPLIT, B_DIM / BM);
    k_gemm<<<grid, 256, DSMEM>>>(x);
    k_fin<<<(B_DIM * OUTC / 8) / 256, 256>>>(bias, out);
}

// round 14
// speedup vs baseline: 1.1474x; 1.0310x over previous
#include <cuda_runtime.h>
#include <cuda_fp16.h>
#include <cstdint>

// ---------------------------------------------------------------------------
// DWT_Features on GB300 (sm_103 PTX: mma.sync path):
//   g_Mh:   84x64 DWT matrix fp16 hi/lo split, built at COMPILE TIME
//   k_weff: W_eff = M^T @ Ws per sn via mma.sync (2-pass Mh+Ml), fp16 out
//   k_gemm: split-K=4 partial GEMM, single-pass fp16, BM=128 BN=128 BK=32
//   k_fin:  out = leaky(p0+p1+p2+p3 + bias)
// ---------------------------------------------------------------------------

#define B_DIM    2048
#define SW_DIM   4
#define KF       128
#define DWT_LEN  84
#define KDIM     4096
#define KSPLIT   4
#define KQ       (KDIM / KSPLIT)   // 1024
#define OUTC     512
#define BK       32
#define NCHUNK   (KQ / BK)         // 32
#define BM       128

#define ROWB     80
#define TILEB    10240
#define AOFF(j)  ((j) * TILEB)
#define BOFF(j)  (2 * TILEB + (j) * TILEB)
#define DSMEM    (5 * TILEB)       // 51200

// ---------------------------------------------------------------------------
// Compile-time DWT matrix (verified logic R7-R12) + fp16 hi/lo tables.
// ---------------------------------------------------------------------------
struct MTab { float m[DWT_LEN * 64]; };

constexpr float DEC_LO[8] = {
    -0.010597401784997278f,  0.032883011666982945f,  0.030841381835986965f,
    -0.18703481171888114f,  -0.02798376941698385f,   0.6308807679295904f,
     0.7148465705525415f,    0.23037781330885523f };
constexpr float DEC_HI[8] = {
    -0.23037781330885523f,   0.7148465705525415f,   -0.6308807679295904f,
    -0.02798376941698385f,   0.18703481171888114f,   0.030841381835986965f,
    -0.032883011666982945f, -0.010597401784997278f };

constexpr MTab build_m() {
    MTab t{};
    float L1[35][64] = {};
    float L2[21][64] = {};
    for (int j = 0; j < 35; j++)
        for (int tau = 0; tau < 64; tau++) {
            float sl = 0.f, sh = 0.f;
            for (int i = 0; i < 8; i++) {
                int idx = 2 * j + i - 6;
                if (idx < 0) idx = -idx;
                if (idx > 63) idx = 126 - idx;
                if (idx == tau) { sl += DEC_LO[7 - i]; sh += DEC_HI[7 - i]; }
            }
            L1[j][tau] = sl;
            t.m[(14 + j) * 64 + tau] = sh;
        }
    for (int j = 0; j < 21; j++)
        for (int tau = 0; tau < 64; tau++) {
            float sl = 0.f, sh = 0.f;
            for (int i = 0; i < 8; i++) {
                int idx = 2 * j + i - 6;
                if (idx < 0) idx = -idx;
                if (idx > 35) idx = 70 - idx;
                if (idx < 35) {
                    float v = L1[idx][tau];
                    sl += v * DEC_LO[7 - i];
                    sh += v * DEC_HI[7 - i];
                }
            }
            L2[j][tau] = sl;
            t.m[(49 + j) * 64 + tau] = sh;
        }
    for (int j = 0; j < 14; j++)
        for (int tau = 0; tau < 64; tau++) {
            float sl = 0.f, sh = 0.f;
            for (int i = 0; i < 8; i++) {
                int idx = 2 * j + i - 6;
                if (idx < 0) idx = -idx;
                if (idx > 21) idx = 42 - idx;
                if (idx < 21) {
                    float v = L2[idx][tau];
                    sl += v * DEC_LO[7 - i];
                    sh += v * DEC_HI[7 - i];
                }
            }
            t.m[j * 64 + tau] = sl;
            t.m[(70 + j) * 64 + tau] = sh;
        }
    return t;
}

// constexpr fp32 -> fp16 (round-to-nearest-even, subnormal-correct)
constexpr uint16_t f2h(float f) {
    if (f == 0.f) return 0;
    uint16_t sign = 0; float a = f;
    if (f < 0.f) { sign = 0x8000; a = -f; }
    int e = 0; float p = 1.f;
    while (a >= 2.f * p) { p *= 2.f; e++; }
    while (a < p)        { p *= 0.5f; e--; }
    if (e >= 16) return (uint16_t)(sign | 0x7C00);
    if (e >= -14) {
        float scaled = (a / p) * 1024.f;           // [1024, 2048), exact ops
        int mi = (int)scaled;
        float rem = scaled - (float)mi;
        if (rem > 0.5f || (rem == 0.5f && (mi & 1))) mi++;
        if (mi == 2048) { mi = 1024; e++; if (e >= 16) return (uint16_t)(sign | 0x7C00); }
        return (uint16_t)(sign | ((e + 15) << 10) | (mi - 1024));
    }
    float scaled = a * 16777216.f;                 // a * 2^24
    int mi = (int)scaled;
    float rem = scaled - (float)mi;
    if (rem > 0.5f || (rem == 0.5f && (mi & 1))) mi++;
    if (mi >= 1024) return (uint16_t)(sign | (1 << 10));
    return (uint16_t)(sign | mi);
}
constexpr float h2f(uint16_t h) {
    int exp = (h >> 10) & 31; int man = h & 1023;
    float v = 0.f;
    if (exp == 0) v = (float)man * 5.9604644775390625e-08f;   // 2^-24
    else {
        int e = exp - 15; float p = 1.f;
        if (e >= 0) for (int i = 0; i < e; i++) p *= 2.f;
        else        for (int i = 0; i < -e; i++) p *= 0.5f;
        v = (1.f + (float)man / 1024.f) * p;
    }
    return (h & 0x8000) ? -v : v;
}

// fp16 hi/lo tables in the exact smem layout: [tau][104 t-cols] (208 B rows)
struct alignas(16) MHTab { uint16_t h[64 * 104]; uint16_t l[64 * 104]; };
constexpr MHTab build_mh() {
    MTab t = build_m();
    MHTab o{};
    for (int tau = 0; tau < 64; tau++)
        for (int k = 0; k < 104; k++) {
            float v = (k < DWT_LEN) ? t.m[k * 64 + tau] : 0.f;
            uint16_t hb = f2h(v);
            o.h[tau * 104 + k] = hb;
            o.l[tau * 104 + k] = f2h(v - h2f(hb));
        }
    return o;
}

__device__ const MHTab g_Mh = build_mh();

__device__ __align__(16) __half g_W[SW_DIM * KF * KDIM];          // [s*128+n][k]
__device__ __align__(16) float g_part[KSPLIT][B_DIM][OUTC];       // 16.8 MB

// ---------------------------------------------------------------------------
__device__ __forceinline__ uint32_t smem_u32(const void* p) {
    uint32_t a;
    asm("{ .reg .u64 t; cvta.to.shared.u64 t, %1; cvt.u32.u64 %0, t; }"
        : "=r"(a) : "l"(p));
    return a;
}
__device__ __forceinline__ void cp16(uint32_t dst, const void* src) {
    asm volatile("cp.async.cg.shared.global [%0], [%1], 16;"
                 :: "r"(dst), "l"(src) : "memory");
}
__device__ __forceinline__ void ldsm4(uint32_t* r, uint32_t addr) {
    asm volatile("ldmatrix.sync.aligned.m8n8.x4.shared.b16 {%0,%1,%2,%3}, [%4];"
                 : "=r"(r[0]), "=r"(r[1]), "=r"(r[2]), "=r"(r[3]) : "r"(addr));
}
__device__ __forceinline__ void ldsm4t(uint32_t* r, uint32_t addr) {
    asm volatile("ldmatrix.sync.aligned.m8n8.x4.trans.shared.b16 {%0,%1,%2,%3}, [%4];"
                 : "=r"(r[0]), "=r"(r[1]), "=r"(r[2]), "=r"(r[3]) : "r"(addr));
}
__device__ __forceinline__ void mma_f16(float* c, const uint32_t* a,
                                        const uint32_t* b) {
    asm volatile(
        "mma.sync.aligned.m16n8k16.row.col.f32.f16.f16.f32 "
        "{%0,%1,%2,%3}, {%4,%5,%6,%7}, {%8,%9}, {%0,%1,%2,%3};"
        : "+f"(c[0]), "+f"(c[1]), "+f"(c[2]), "+f"(c[3])
        : "r"(a[0]), "r"(a[1]), "r"(a[2]), "r"(a[3]), "r"(b[0]), "r"(b[1]));
}

// ---------------------------------------------------------------------------
// k_weff: W_eff[sn] = M^T @ Ws via mma.sync, 2 passes (Mh, Ml), fp32 accum.
// 128 threads = 4 warps; warp w owns tau rows w*16..+15, all 64 hw cols.
// smem: Mh [64][104] fp16 (13312) | Ml (13312) | Ws [96][72] fp16 (13824)
// ---------------------------------------------------------------------------
#define MROWB     208
#define WROWB     144
#define SM_MH     0
#define SM_ML     13312
#define SM_WS     26624
#define WEFF_SMEM 40448

__global__ void __launch_bounds__(128)
k_weff(const float* __restrict__ cw) {
    extern __shared__ char wsm[];
    const int tid = threadIdx.x;
    const int wid = tid >> 5, lid = tid & 31;
    const int sn = blockIdx.x;
    const uint32_t sbase = smem_u32(wsm);

    // async-load M hi/lo tables (832 x 16B each)
    for (int i = tid; i < 832; i += 128) {
        cp16(sbase + SM_MH + i * 16, g_Mh.h + i * 8);
        cp16(sbase + SM_ML + i * 16, g_Mh.l + i * 8);
    }
    asm volatile("cp.async.commit_group;" ::: "memory");

    // zero Ws pad rows 84..95 (12 rows x 144 B = 108 x 16B)
    for (int i = tid; i < 108; i += 128)
        *(uint4*)(wsm + SM_WS + 84 * WROWB + i * 16) = make_uint4(0, 0, 0, 0);

    // load + convert Ws: cw slice [84][64] fp32 -> fp16 [96][72]
    const float* src = cw + (size_t)sn * (DWT_LEN * 64);
    for (int idx = tid; idx < DWT_LEN * 16; idx += 128) {
        int t = idx >> 4, c4 = (idx & 15) * 4;
        float4 v = *(const float4*)(src + t * 64 + c4);
        __half2 h01 = __float22half2_rn(make_float2(v.x, v.y));
        __half2 h23 = __float22half2_rn(make_float2(v.z, v.w));
        *(uint2*)(wsm + SM_WS + t * WROWB + c4 * 2) =
            make_uint2(*(uint32_t*)&h01, *(uint32_t*)&h23);
    }
    asm volatile("cp.async.wait_group 0;" ::: "memory");
    __syncthreads();

    const int q = lid >> 3, r = lid & 7;
    const uint32_t aH = sbase + SM_MH
        + (wid * 16 + (q & 1) * 8 + r) * MROWB + (q >> 1) * 16;
    const uint32_t aL = aH + (SM_ML - SM_MH);
    const uint32_t bA = sbase + SM_WS
        + ((q & 1) * 8 + r) * WROWB + (q >> 1) * 16;

    float acc[8][4];
    #pragma unroll
    for (int a = 0; a < 8; a++)
        #pragma unroll
        for (int c = 0; c < 4; c++) acc[a][c] = 0.f;

    #pragma unroll
    for (int ks = 0; ks < 6; ks++) {
        uint32_t Ah[4], Al[4], Bf[4][4];
        ldsm4(Ah, aH + ks * 32);
        ldsm4(Al, aL + ks * 32);
        #pragma unroll
        for (int nb = 0; nb < 4; nb++)
            ldsm4t(Bf[nb], bA + ks * 16 * WROWB + nb * 32);
        #pragma unroll
        for (int nf = 0; nf < 8; nf++)
            mma_f16(acc[nf], Ah, Bf[nf >> 1] + (nf & 1) * 2);
        #pragma unroll
        for (int nf = 0; nf < 8; nf++)
            mma_f16(acc[nf], Al, Bf[nf >> 1] + (nf & 1) * 2);
    }

    // store fp16 W_eff[sn][tau*64 + hw]
    __half* dst = g_W + (size_t)sn * KDIM;
    const int row = wid * 16 + (lid >> 2);
    const int cb = (lid & 3) * 2;
    #pragma unroll
    for (int nf = 0; nf < 8; nf++) {
        int col = nf * 8 + cb;
        __half2 lo = __float22half2_rn(make_float2(acc[nf][0], acc[nf][1]));
        __half2 hi = __float22half2_rn(make_float2(acc[nf][2], acc[nf][3]));
        *(__half2*)&dst[row * 64 + col] = lo;
        *(__half2*)&dst[(row + 8) * 64 + col] = hi;
    }
}

// ---------------------------------------------------------------------------
// k_gemm: BM=128, BN=128, BK=32, split-K=4 (verified R10/R12, unchanged).
// ---------------------------------------------------------------------------
#define ISSUE_B(K0, STOFF) do {                                              \
    uint32_t _st = sbase + (STOFF);                                          \
    _Pragma("unroll")                                                        \
    for (int _it = 0; _it < 2; _it++) {                                      \
        int _idx = tid + _it * 256;                                          \
        int _n = _idx >> 2, _seg = _idx & 3;                                 \
        cp16(_st + _n * ROWB + _seg * 16,                                    \
             WB + (size_t)_n * KDIM + (K0) + _seg * 8);                      \
    }                                                                        \
    asm volatile("cp.async.commit_group;" ::: "memory");                     \
} while (0)

#define LDG_A(K0) do {                                                       \
    _Pragma("unroll")                                                        \
    for (int _it = 0; _it < 4; _it++) {                                      \
        int _idx = tid + _it * 256;                                          \
        int _row = _idx >> 3, _seg = _idx & 7;                               \
        areg[_it] = *(const float4*)(Abase +                                 \
            (size_t)_row * (SW_DIM * KDIM) + (K0) + _seg * 4);               \
    }                                                                        \
} while (0)

#define STS_A(STOFF) do {                                                    \
    char* _pb = sm + (STOFF);                                                \
    _Pragma("unroll")                                                        \
    for (int _it = 0; _it < 4; _it++) {                                      \
        int _idx = tid + _it * 256;                                          \
        int _row = _idx >> 3, _seg = _idx & 7;                               \
        float4 _v = areg[_it];                                               \
        __half2 _h01 = __float22half2_rn(make_float2(_v.x, _v.y));           \
        __half2 _h23 = __float22half2_rn(make_float2(_v.z, _v.w));           \
        *(uint2*)(_pb + _row * ROWB + _seg * 8) =                            \
            make_uint2(*(uint32_t*)&_h01, *(uint32_t*)&_h23);                \
    }                                                                        \
} while (0)

__global__ void __launch_bounds__(256, 2)
k_gemm(const float* __restrict__ x) {
    extern __shared__ char sm[];
    const int tid = threadIdx.x;
    const int wid = tid >> 5, lid = tid & 31;
    const int s = blockIdx.x >> 2;
    const int ks = blockIdx.x & 3;
    const int m0 = blockIdx.y * BM;
    const int kbase = ks * KQ;
    const int wm = wid & 1, wn = wid >> 1;

    const uint32_t sbase = smem_u32(sm);
    const float* Abase = x + (size_t)m0 * (SW_DIM * KDIM) + (size_t)s * KDIM
                         + kbase;
    const __half* WB = g_W + (size_t)s * KF * KDIM + kbase;

    const int q = lid >> 3, r = lid & 7;
    const uint32_t laneA = (wm * 64 + (q & 1) * 8 + r) * ROWB + (q >> 1) * 16;
    const uint32_t laneB = (wn * 32 + (q >> 1) * 8 + r) * ROWB + (q & 1) * 16;

    float acc[4][4][4];
    #pragma unroll
    for (int a = 0; a < 4; a++)
        #pragma unroll
        for (int b = 0; b < 4; b++)
            #pragma unroll
            for (int c = 0; c < 4; c++) acc[a][b][c] = 0.f;

    float4 areg[4];

    ISSUE_B(0, BOFF(0));
    ISSUE_B(BK, BOFF(1));
    LDG_A(0);
    STS_A(AOFF(0));
    LDG_A(BK);
    asm volatile("cp.async.wait_group 1;" ::: "memory");
    __syncthreads();

    for (int i = 0; i < NCHUNK; i++) {
        if (i + 2 < NCHUNK) ISSUE_B((i + 2) * BK, BOFF((i + 2) % 3));

        const uint32_t stA = sbase + AOFF(i & 1);
        const uint32_t stB = sbase + BOFF(i % 3);
        #pragma unroll
        for (int kk = 0; kk < 2; kk++) {
            const uint32_t ka = kk * 32;
            uint32_t Af[4][4], B0[4], B1[4];
            ldsm4(B0, stB + laneB + ka);
            ldsm4(B1, stB + laneB + ka + 16 * ROWB);
            #pragma unroll
            for (int mf = 0; mf < 4; mf++)
                ldsm4(Af[mf], stA + laneA + mf * (16 * ROWB) + ka);
            #pragma unroll
            for (int mf = 0; mf < 4; mf++) {
                #pragma unroll
                for (int nf = 0; nf < 4; nf++) {
                    const uint32_t* bb = ((nf & 2) ? B1 : B0) + (nf & 1) * 2;
                    mma_f16(acc[mf][nf], Af[mf], bb);
                }
            }
        }

        if (i + 1 < NCHUNK) STS_A(AOFF((i + 1) & 1));
        if (i + 2 < NCHUNK) {
            LDG_A((i + 2) * BK);
            asm volatile("cp.async.wait_group 1;" ::: "memory");
        } else {
            asm volatile("cp.async.wait_group 0;" ::: "memory");
        }
        __syncthreads();
    }

    const int g = lid >> 2, tc = lid & 3;
    float* pbase = &g_part[ks][0][0];
    #pragma unroll
    for (int mf = 0; mf < 4; mf++) {
        const int row = m0 + wm * 64 + mf * 16 + g;
        #pragma unroll
        for (int nf = 0; nf < 4; nf++) {
            const int col = s * KF + wn * 32 + nf * 8 + tc * 2;
            *(float2*)&pbase[(size_t)row * OUTC + col] =
                make_float2(acc[mf][nf][0], acc[mf][nf][1]);
            *(float2*)&pbase[(size_t)(row + 8) * OUTC + col] =
                make_float2(acc[mf][nf][2], acc[mf][nf][3]);
        }
    }
}

// ---------------------------------------------------------------------------
// finalize: out = leaky(p0+p1+p2+p3 + bias); 4 float4 per thread
// ---------------------------------------------------------------------------
__global__ void __launch_bounds__(256)
k_fin(const float* __restrict__ bias, float* __restrict__ out) {
    #pragma unroll
    for (int u = 0; u < 4; u++) {
        int i = (blockIdx.x * 4 + u) * 256 + threadIdx.x;   // float4 index
        float4 a = *(const float4*)(&g_part[0][0][0] + (size_t)i * 4);
        float4 b = *(const float4*)(&g_part[1][0][0] + (size_t)i * 4);
        float4 c = *(const float4*)(&g_part[2][0][0] + (size_t)i * 4);
        float4 d = *(const float4*)(&g_part[3][0][0] + (size_t)i * 4);
        int col = (i * 4) & (OUTC - 1);
        float4 bb = *(const float4*)&bias[col];
        float v0 = (a.x + b.x) + (c.x + d.x) + bb.x;
        float v1 = (a.y + b.y) + (c.y + d.y) + bb.y;
        float v2 = (a.z + b.z) + (c.z + d.z) + bb.z;
        float v3 = (a.w + b.w) + (c.w + d.w) + bb.w;
        v0 = v0 > 0.f ? v0 : 0.01f * v0;
        v1 = v1 > 0.f ? v1 : 0.01f * v1;
        v2 = v2 > 0.f ? v2 : 0.01f * v2;
        v3 = v3 > 0.f ? v3 : 0.01f * v3;
        *(float4*)&out[(size_t)i * 4] = make_float4(v0, v1, v2, v3);
    }
}

// ---------------------------------------------------------------------------
extern "C" void kernel_launch(void* const* d_in, const int* in_sizes, int n_in,
                              void* d_out, int out_size) {
    const float* x    = (const float*)d_in[0];   // [2048,1,256,8,8]
    const float* cw   = (const float*)d_in[1];   // [4,128,84,8,8]
    const float* bias = (const float*)d_in[2];   // [4,128]
    float* out = (float*)d_out;                  // [2048,512]

    cudaFuncSetAttribute(k_weff, cudaFuncAttributeMaxDynamicSharedMemorySize,
                         WEFF_SMEM);
    cudaFuncSetAttribute(k_gemm, cudaFuncAttributeMaxDynamicSharedMemorySize,
                         DSMEM);

    k_weff<<<SW_DIM * KF, 128, WEFF_SMEM>>>(cw);
    dim3 grid(SW_DIM * KSPLIT, B_DIM / BM);
    k_gemm<<<grid, 256, DSMEM>>>(x);
    k_fin<<<(B_DIM * OUTC / 16) / 256, 256>>>(bias, out);
}